// round 5
// baseline (speedup 1.0000x reference)
#include <cuda_runtime.h>
#include <cuda_bf16.h>
#include <cstdint>
#include <cstddef>

// ============================================================================
// LinearDecoder: out_mean = mean @ W^T + b ; out_logv = log( exp(logvar) @ (W*W)^T )
// B=131072, X=128, Y=512.  Plain-sm_103 PTX (no tcgen05 in this harness).
// mma.sync.m16n8k16 bf16, fp32 hi/lo split (hh+hl+lh).
// Round-5: 3 CTAs/SM (regs <= 84 via __launch_bounds__(256,3)), staggered
// split-term schedule to keep the mainloop live set under the reg budget.
// ============================================================================

static constexpr int XD  = 128;   // K
static constexpr int YD  = 512;   // N total
static constexpr int MT  = 128;   // M rows per CTA
static constexpr int TPB = 256;

// B fragments: [kind: Whi,Wlo,W2hi,W2lo][h: 32-col slice 0..15][ks 0..7]
//              [p 0..1][lane 0..31][16B = b0,b1 of tiles ni=2p, 2p+1]
__device__ __align__(16) unsigned char g_Bfrag[4][16][8][2][32][16];

// SMEM: bias + A hi/lo tiles
static constexpr int OFF_BIAS = 0;                 // 512 floats
static constexpr int OFF_AH   = 4096;              // A hi tile 32KB
static constexpr int OFF_AL   = OFF_AH + 32768;    // A lo tile 32KB
static constexpr int SMEM_SIZE = OFF_AL + 32768;   // 69632 B -> 3 CTAs/SM

// ---------------------------------------------------------------------------
// helpers
// ---------------------------------------------------------------------------
__device__ __forceinline__ uint32_t smem_u32(const void* p) {
    uint32_t a;
    asm("{ .reg .u64 t; cvta.to.shared.u64 t, %1; cvt.u32.u64 %0, t; }"
        : "=r"(a) : "l"(p));
    return a;
}

// A tile: 128 rows x 256B, 16B chunks XOR-swizzled with (r&7)
__device__ __forceinline__ uint32_t tile_off(int r, int k0) {
    uint32_t ck = (uint32_t)(k0 >> 3) ^ (uint32_t)(r & 7);
    return (uint32_t)r * 256u + ck * 16u + (uint32_t)(k0 & 7) * 2u;
}

__device__ __forceinline__ float bf16rt(float x) {
    return __bfloat162float(__float2bfloat16(x));
}

__device__ __forceinline__ uint32_t pack2(float a, float b) {
    __nv_bfloat162 t = __floats2bfloat162_rn(a, b);
    return *reinterpret_cast<uint32_t*>(&t);
}

__device__ __forceinline__ void ldsm4(uint32_t* r, uint32_t addr) {
    asm volatile("ldmatrix.sync.aligned.m8n8.x4.shared.b16 {%0,%1,%2,%3}, [%4];"
                 : "=r"(r[0]), "=r"(r[1]), "=r"(r[2]), "=r"(r[3]) : "r"(addr));
}

__device__ __forceinline__ void mma16816(float* c, const uint32_t* a,
                                         uint32_t b0, uint32_t b1) {
    asm volatile(
        "mma.sync.aligned.m16n8k16.row.col.f32.bf16.bf16.f32 "
        "{%0,%1,%2,%3}, {%4,%5,%6,%7}, {%8,%9}, {%0,%1,%2,%3};"
        : "+f"(c[0]), "+f"(c[1]), "+f"(c[2]), "+f"(c[3])
        : "r"(a[0]), "r"(a[1]), "r"(a[2]), "r"(a[3]), "r"(b0), "r"(b1));
}

// ---------------------------------------------------------------------------
// Prep kernel: bake W / W*W hi/lo into MMA-fragment order.
// ---------------------------------------------------------------------------
__global__ void prep_w_kernel(const float* __restrict__ W) {
    int id = blockIdx.x * blockDim.x + threadIdx.x;   // 0 .. 16383
    if (id >= 2 * 16 * 8 * 2 * 32) return;
    const int lane   = id & 31;
    const int p      = (id >> 5) & 1;
    const int ks     = (id >> 6) & 7;
    const int h      = (id >> 9) & 15;
    const int branch = id >> 13;                      // 0 = W, 1 = W*W

    uint32_t hi[4], lo[4];
    #pragma unroll
    for (int w = 0; w < 4; ++w) {
        int ni = 2 * p + (w >> 1);
        int n  = h * 32 + ni * 8 + (lane >> 2);
        int k  = ks * 16 + (w & 1) * 8 + (lane & 3) * 2;
        float w0 = W[n * XD + k];
        float w1 = W[n * XD + k + 1];
        if (branch) { w0 *= w0; w1 *= w1; }
        float h0 = bf16rt(w0), h1 = bf16rt(w1);
        hi[w] = pack2(h0, h1);
        lo[w] = pack2(w0 - h0, w1 - h1);
    }
    *(uint4*)&g_Bfrag[branch * 2][h][ks][p][lane][0] =
        make_uint4(hi[0], hi[1], hi[2], hi[3]);
    *(uint4*)&g_Bfrag[branch * 2 + 1][h][ks][p][lane][0] =
        make_uint4(lo[0], lo[1], lo[2], lo[3]);
}

// ---------------------------------------------------------------------------
// Main kernel: CTA = 128 batch rows; warp = 32(M) x 32(N) per 64-col chunk
// ---------------------------------------------------------------------------
__global__ void __launch_bounds__(TPB, 3)
decoder_kernel(const float* __restrict__ mean, const float* __restrict__ logvar,
               const float* __restrict__ bias,
               float* __restrict__ out_mean, float* __restrict__ out_logv) {
    extern __shared__ __align__(16) char smem[];
    const uint32_t sb = smem_u32(smem);
    const int tid = threadIdx.x;
    const int t   = tid & 31;
    const int wid = tid >> 5;
    const int wm  = wid & 3;       // M group: rows wm*32 .. wm*32+31
    const int wn  = wid >> 2;      // N half within 64-col chunk
    const int row0 = blockIdx.x * MT;

    for (int i = tid; i < YD; i += TPB)
        ((float*)(smem + OFF_BIAS))[i] = bias[i];

    // Precompute A ldsm base offsets (per mi); per-ks advance via XOR
    uint32_t a_off[2];
    #pragma unroll
    for (int mi = 0; mi < 2; ++mi) {
        uint32_t row = (uint32_t)(wm * 32 + mi * 16 + (t & 15));
        a_off[mi] = row * 256u + (((uint32_t)(t >> 4) ^ (row & 7u)) << 4);
    }

    for (int branch = 0; branch < 2; ++branch) {
        if (branch) __syncthreads();   // A tiles about to be rewritten
        // ---- A conversion -> hi/lo bf16 swizzled tiles ----
        const float* src = branch ? logvar : mean;
        for (int idx = tid; idx < MT * (XD / 2); idx += TPB) {
            int r  = idx >> 6;
            int k0 = (idx & 63) * 2;
            float2 v = *(const float2*)(src + (size_t)(row0 + r) * XD + k0);
            float v0 = v.x, v1 = v.y;
            if (branch) { v0 = __expf(v0); v1 = __expf(v1); }
            uint32_t sw = tile_off(r, k0);
            float h0 = bf16rt(v0), h1 = bf16rt(v1);
            *(uint32_t*)(smem + OFF_AH + sw) = pack2(h0, h1);
            *(uint32_t*)(smem + OFF_AL + sw) = pack2(v0 - h0, v1 - h1);
        }
        __syncthreads();

        for (int nc = 0; nc < 8; ++nc) {
            const int h = nc * 2 + wn;
            // uint4 element index: (((kind*16 + h)*8 + ks)*2 + p)*32 + lane
            const uint4* bH = (const uint4*)g_Bfrag +
                (size_t)((branch * 2) * 16 + h) * (8 * 2 * 32) + t;
            const uint4* bL = (const uint4*)g_Bfrag +
                (size_t)((branch * 2 + 1) * 16 + h) * (8 * 2 * 32) + t;

            float c[2][4][4] = {};

            #pragma unroll
            for (int ks = 0; ks < 8; ++ks) {
                const uint32_t kxor = ((uint32_t)(2 * ks) << 4);
                // B fragments via coalesced LDG.128 (L1-resident)
                uint4 h0 = bH[ks * 64];        // p=0: tiles ni 0,1
                uint4 h1 = bH[ks * 64 + 32];   // p=1: tiles ni 2,3
                const uint32_t bh[8] = {h0.x, h0.y, h0.z, h0.w,
                                        h1.x, h1.y, h1.z, h1.w};
                uint4 l0 = bL[ks * 64];
                uint4 l1 = bL[ks * 64 + 32];
                const uint32_t bl[8] = {l0.x, l0.y, l0.z, l0.w,
                                        l1.x, l1.y, l1.z, l1.w};

                // Staggered schedule keeps live regs low:
                // per mi: ldsm ah -> hh + hl terms -> ldsm al -> lh term.
                #pragma unroll
                for (int mi = 0; mi < 2; ++mi) {
                    const uint32_t off = a_off[mi] ^ kxor;
                    uint32_t a[4];
                    ldsm4(a, sb + OFF_AH + off);
                    #pragma unroll
                    for (int ni = 0; ni < 4; ++ni) {
                        mma16816(c[mi][ni], a, bh[ni * 2], bh[ni * 2 + 1]);
                        mma16816(c[mi][ni], a, bl[ni * 2], bl[ni * 2 + 1]);
                    }
                    ldsm4(a, sb + OFF_AL + off);
                    #pragma unroll
                    for (int ni = 0; ni < 4; ++ni)
                        mma16816(c[mi][ni], a, bh[ni * 2], bh[ni * 2 + 1]);
                }
            }

            // ---- epilogue (A tile untouched; no sync needed) ----
            const float* bs = (const float*)(smem + OFF_BIAS);
            #pragma unroll
            for (int mi = 0; mi < 2; ++mi) {
                const int r0 = row0 + wm * 32 + mi * 16 + (t >> 2);
                #pragma unroll
                for (int ni = 0; ni < 4; ++ni) {
                    const int col = nc * 64 + wn * 32 + ni * 8 + (t & 3) * 2;
                    float2 v0, v1;
                    v0.x = c[mi][ni][0]; v0.y = c[mi][ni][1];
                    v1.x = c[mi][ni][2]; v1.y = c[mi][ni][3];
                    if (branch == 0) {
                        float b0 = bs[col], b1 = bs[col + 1];
                        v0.x += b0; v0.y += b1;
                        v1.x += b0; v1.y += b1;
                        *(float2*)(out_mean + (size_t)r0 * YD + col)       = v0;
                        *(float2*)(out_mean + (size_t)(r0 + 8) * YD + col) = v1;
                    } else {
                        v0.x = __logf(v0.x); v0.y = __logf(v0.y);
                        v1.x = __logf(v1.x); v1.y = __logf(v1.y);
                        *(float2*)(out_logv + (size_t)r0 * YD + col)       = v0;
                        *(float2*)(out_logv + (size_t)(r0 + 8) * YD + col) = v1;
                    }
                }
            }
        }
    }
}

// ---------------------------------------------------------------------------
// Launch
// ---------------------------------------------------------------------------
extern "C" void kernel_launch(void* const* d_in, const int* in_sizes, int n_in,
                              void* d_out, int out_size) {
    const float* mean   = (const float*)d_in[0];
    const float* logvar = (const float*)d_in[1];
    const float* W      = (const float*)d_in[2];
    const float* bias   = (const float*)d_in[3];

    const int B = in_sizes[0] / XD;   // 131072
    float* out_mean = (float*)d_out;
    float* out_logv = out_mean + (size_t)B * YD;

    prep_w_kernel<<<64, TPB>>>(W);

    cudaFuncSetAttribute(decoder_kernel,
                         cudaFuncAttributeMaxDynamicSharedMemorySize, SMEM_SIZE);
    decoder_kernel<<<B / MT, TPB, SMEM_SIZE>>>(mean, logvar, bias,
                                               out_mean, out_logv);
}

// round 6
// speedup vs baseline: 1.2666x; 1.2666x over previous
#include <cuda_runtime.h>
#include <cuda_bf16.h>
#include <cstdint>
#include <cstddef>

// ============================================================================
// LinearDecoder: out_mean = mean @ W^T + b ; out_logv = log( exp(logvar) @ (W*W)^T )
// B=131072, X=128, Y=512.  Plain-sm_103 PTX (no tcgen05 in this harness).
// mma.sync.m16n8k16 bf16, fp32 hi/lo split (hh+hl+lh).
// Round-6: round-4 structure (2 CTAs/SM) + term-major MMA ordering (breaks
// serial accumulator chains) + software-pipelined B LDGs.
// ============================================================================

static constexpr int XD  = 128;   // K
static constexpr int YD  = 512;   // N total
static constexpr int MT  = 128;   // M rows per CTA
static constexpr int TPB = 256;

// B fragments: [kind: Whi,Wlo,W2hi,W2lo][h: 32-col slice 0..15][ks 0..7]
//              [p 0..1][lane 0..31][16B = b0,b1 of tiles ni=2p, 2p+1]
__device__ __align__(16) unsigned char g_Bfrag[4][16][8][2][32][16];

// SMEM: bias + A hi/lo tiles
static constexpr int OFF_BIAS = 0;                 // 512 floats
static constexpr int OFF_AH   = 4096;              // A hi tile 32KB
static constexpr int OFF_AL   = OFF_AH + 32768;    // A lo tile 32KB
static constexpr int SMEM_SIZE = OFF_AL + 32768;   // 69632 B

// ---------------------------------------------------------------------------
// helpers
// ---------------------------------------------------------------------------
__device__ __forceinline__ uint32_t smem_u32(const void* p) {
    uint32_t a;
    asm("{ .reg .u64 t; cvta.to.shared.u64 t, %1; cvt.u32.u64 %0, t; }"
        : "=r"(a) : "l"(p));
    return a;
}

// A tile: 128 rows x 256B, 16B chunks XOR-swizzled with (r&7)
__device__ __forceinline__ uint32_t tile_off(int r, int k0) {
    uint32_t ck = (uint32_t)(k0 >> 3) ^ (uint32_t)(r & 7);
    return (uint32_t)r * 256u + ck * 16u + (uint32_t)(k0 & 7) * 2u;
}

__device__ __forceinline__ float bf16rt(float x) {
    return __bfloat162float(__float2bfloat16(x));
}

__device__ __forceinline__ uint32_t pack2(float a, float b) {
    __nv_bfloat162 t = __floats2bfloat162_rn(a, b);
    return *reinterpret_cast<uint32_t*>(&t);
}

__device__ __forceinline__ void ldsm4(uint32_t* r, uint32_t addr) {
    asm volatile("ldmatrix.sync.aligned.m8n8.x4.shared.b16 {%0,%1,%2,%3}, [%4];"
                 : "=r"(r[0]), "=r"(r[1]), "=r"(r[2]), "=r"(r[3]) : "r"(addr));
}

__device__ __forceinline__ void mma16816(float* c, const uint32_t* a,
                                         uint32_t b0, uint32_t b1) {
    asm volatile(
        "mma.sync.aligned.m16n8k16.row.col.f32.bf16.bf16.f32 "
        "{%0,%1,%2,%3}, {%4,%5,%6,%7}, {%8,%9}, {%0,%1,%2,%3};"
        : "+f"(c[0]), "+f"(c[1]), "+f"(c[2]), "+f"(c[3])
        : "r"(a[0]), "r"(a[1]), "r"(a[2]), "r"(a[3]), "r"(b0), "r"(b1));
}

// ---------------------------------------------------------------------------
// Prep kernel: bake W / W*W hi/lo into MMA-fragment order.
// ---------------------------------------------------------------------------
__global__ void prep_w_kernel(const float* __restrict__ W) {
    int id = blockIdx.x * blockDim.x + threadIdx.x;   // 0 .. 16383
    if (id >= 2 * 16 * 8 * 2 * 32) return;
    const int lane   = id & 31;
    const int p      = (id >> 5) & 1;
    const int ks     = (id >> 6) & 7;
    const int h      = (id >> 9) & 15;
    const int branch = id >> 13;                      // 0 = W, 1 = W*W

    uint32_t hi[4], lo[4];
    #pragma unroll
    for (int w = 0; w < 4; ++w) {
        int ni = 2 * p + (w >> 1);
        int n  = h * 32 + ni * 8 + (lane >> 2);
        int k  = ks * 16 + (w & 1) * 8 + (lane & 3) * 2;
        float w0 = W[n * XD + k];
        float w1 = W[n * XD + k + 1];
        if (branch) { w0 *= w0; w1 *= w1; }
        float h0 = bf16rt(w0), h1 = bf16rt(w1);
        hi[w] = pack2(h0, h1);
        lo[w] = pack2(w0 - h0, w1 - h1);
    }
    *(uint4*)&g_Bfrag[branch * 2][h][ks][p][lane][0] =
        make_uint4(hi[0], hi[1], hi[2], hi[3]);
    *(uint4*)&g_Bfrag[branch * 2 + 1][h][ks][p][lane][0] =
        make_uint4(lo[0], lo[1], lo[2], lo[3]);
}

// ---------------------------------------------------------------------------
// Main kernel: CTA = 128 batch rows; warp = 32(M) x 32(N) per 64-col chunk
// ---------------------------------------------------------------------------
__global__ void __launch_bounds__(TPB, 2)
decoder_kernel(const float* __restrict__ mean, const float* __restrict__ logvar,
               const float* __restrict__ bias,
               float* __restrict__ out_mean, float* __restrict__ out_logv) {
    extern __shared__ __align__(16) char smem[];
    const uint32_t sb = smem_u32(smem);
    const int tid = threadIdx.x;
    const int t   = tid & 31;
    const int wid = tid >> 5;
    const int wm  = wid & 3;       // M group: rows wm*32 .. wm*32+31
    const int wn  = wid >> 2;      // N half within 64-col chunk
    const int row0 = blockIdx.x * MT;

    for (int i = tid; i < YD; i += TPB)
        ((float*)(smem + OFF_BIAS))[i] = bias[i];

    // A ldsm base offsets (per mi); per-ks advance via XOR of chunk index
    uint32_t a_off[2];
    #pragma unroll
    for (int mi = 0; mi < 2; ++mi) {
        uint32_t row = (uint32_t)(wm * 32 + mi * 16 + (t & 15));
        a_off[mi] = row * 256u + (((uint32_t)(t >> 4) ^ (row & 7u)) << 4);
    }

    for (int branch = 0; branch < 2; ++branch) {
        if (branch) __syncthreads();   // A tiles about to be rewritten
        // ---- A conversion -> hi/lo bf16 swizzled tiles ----
        const float* src = branch ? logvar : mean;
        for (int idx = tid; idx < MT * (XD / 2); idx += TPB) {
            int r  = idx >> 6;
            int k0 = (idx & 63) * 2;
            float2 v = *(const float2*)(src + (size_t)(row0 + r) * XD + k0);
            float v0 = v.x, v1 = v.y;
            if (branch) { v0 = __expf(v0); v1 = __expf(v1); }
            uint32_t sw = tile_off(r, k0);
            float h0 = bf16rt(v0), h1 = bf16rt(v1);
            *(uint32_t*)(smem + OFF_AH + sw) = pack2(h0, h1);
            *(uint32_t*)(smem + OFF_AL + sw) = pack2(v0 - h0, v1 - h1);
        }
        __syncthreads();

        for (int nc = 0; nc < 8; ++nc) {
            const int h = nc * 2 + wn;
            // uint4 element index: (((kind*16 + h)*8 + ks)*2 + p)*32 + lane
            const uint4* bH = (const uint4*)g_Bfrag +
                (size_t)((branch * 2) * 16 + h) * (8 * 2 * 32) + t;
            const uint4* bL = (const uint4*)g_Bfrag +
                (size_t)((branch * 2 + 1) * 16 + h) * (8 * 2 * 32) + t;

            float c[2][4][4] = {};

            // prefetch ks=0 B fragments
            uint4 ph0 = bH[0], ph1 = bH[32];
            uint4 pl0 = bL[0], pl1 = bL[32];

            #pragma unroll
            for (int ks = 0; ks < 8; ++ks) {
                const uint32_t bh[8] = {ph0.x, ph0.y, ph0.z, ph0.w,
                                        ph1.x, ph1.y, ph1.z, ph1.w};
                const uint32_t bl[8] = {pl0.x, pl0.y, pl0.z, pl0.w,
                                        pl1.x, pl1.y, pl1.z, pl1.w};
                if (ks < 7) {   // software pipeline: B for ks+1
                    ph0 = bH[(ks + 1) * 64];
                    ph1 = bH[(ks + 1) * 64 + 32];
                    pl0 = bL[(ks + 1) * 64];
                    pl1 = bL[(ks + 1) * 64 + 32];
                }
                // A fragments (independent hi / lo register sets)
                uint32_t ah[8], al[8];
                const uint32_t kxor = ((uint32_t)(2 * ks) << 4);
                ldsm4(&ah[0], sb + OFF_AH + (a_off[0] ^ kxor));
                ldsm4(&ah[4], sb + OFF_AH + (a_off[1] ^ kxor));
                ldsm4(&al[0], sb + OFF_AL + (a_off[0] ^ kxor));
                ldsm4(&al[4], sb + OFF_AL + (a_off[1] ^ kxor));

                // term-major: each accumulator revisited every 8 MMAs
                #pragma unroll
                for (int mi = 0; mi < 2; ++mi)
                    #pragma unroll
                    for (int ni = 0; ni < 4; ++ni)
                        mma16816(c[mi][ni], &ah[mi * 4], bh[ni * 2], bh[ni * 2 + 1]);
                #pragma unroll
                for (int mi = 0; mi < 2; ++mi)
                    #pragma unroll
                    for (int ni = 0; ni < 4; ++ni)
                        mma16816(c[mi][ni], &ah[mi * 4], bl[ni * 2], bl[ni * 2 + 1]);
                #pragma unroll
                for (int mi = 0; mi < 2; ++mi)
                    #pragma unroll
                    for (int ni = 0; ni < 4; ++ni)
                        mma16816(c[mi][ni], &al[mi * 4], bh[ni * 2], bh[ni * 2 + 1]);
            }

            // ---- epilogue (A tile untouched; no sync needed) ----
            const float* bs = (const float*)(smem + OFF_BIAS);
            #pragma unroll
            for (int mi = 0; mi < 2; ++mi) {
                const int r0 = row0 + wm * 32 + mi * 16 + (t >> 2);
                #pragma unroll
                for (int ni = 0; ni < 4; ++ni) {
                    const int col = nc * 64 + wn * 32 + ni * 8 + (t & 3) * 2;
                    float2 v0, v1;
                    v0.x = c[mi][ni][0]; v0.y = c[mi][ni][1];
                    v1.x = c[mi][ni][2]; v1.y = c[mi][ni][3];
                    if (branch == 0) {
                        float b0 = bs[col], b1 = bs[col + 1];
                        v0.x += b0; v0.y += b1;
                        v1.x += b0; v1.y += b1;
                        *(float2*)(out_mean + (size_t)r0 * YD + col)       = v0;
                        *(float2*)(out_mean + (size_t)(r0 + 8) * YD + col) = v1;
                    } else {
                        v0.x = __logf(v0.x); v0.y = __logf(v0.y);
                        v1.x = __logf(v1.x); v1.y = __logf(v1.y);
                        *(float2*)(out_logv + (size_t)r0 * YD + col)       = v0;
                        *(float2*)(out_logv + (size_t)(r0 + 8) * YD + col) = v1;
                    }
                }
            }
        }
    }
}

// ---------------------------------------------------------------------------
// Launch
// ---------------------------------------------------------------------------
extern "C" void kernel_launch(void* const* d_in, const int* in_sizes, int n_in,
                              void* d_out, int out_size) {
    const float* mean   = (const float*)d_in[0];
    const float* logvar = (const float*)d_in[1];
    const float* W      = (const float*)d_in[2];
    const float* bias   = (const float*)d_in[3];

    const int B = in_sizes[0] / XD;   // 131072
    float* out_mean = (float*)d_out;
    float* out_logv = out_mean + (size_t)B * YD;

    prep_w_kernel<<<64, TPB>>>(W);

    cudaFuncSetAttribute(decoder_kernel,
                         cudaFuncAttributeMaxDynamicSharedMemorySize, SMEM_SIZE);
    decoder_kernel<<<B / MT, TPB, SMEM_SIZE>>>(mean, logvar, bias,
                                               out_mean, out_logv);
}

// round 9
// speedup vs baseline: 1.7468x; 1.3792x over previous
#include <cuda_runtime.h>
#include <cuda_fp16.h>
#include <cstdint>
#include <cstddef>

// ============================================================================
// LinearDecoder: out_mean = mean @ W^T + b ; out_logv = log( exp(logvar) @ (W*W)^T )
// B=131072, X=128, Y=512.  Plain-sm_103 PTX (no tcgen05 in this harness).
// Round-7: fp16 2-term split (A = ah+al exact to 2^-23, B single fp16 ->
// error only from B rounding ~1.4e-4 norm-rel) + 2Mx4N warp tiling
// (B LDG redundancy 4x -> 2x). Cuts L1 bytes ~56% and MMAs 33% vs round-6.
// ============================================================================

static constexpr int XD  = 128;   // K
static constexpr int YD  = 512;   // N total
static constexpr int MT  = 128;   // M rows per CTA
static constexpr int TPB = 256;

// B fragments (fp16): [branch: W, W*W][h: 32-col slice 0..15][ks 0..7]
//                     [p 0..1][lane 0..31][16B = b0,b1 of tiles ni=2p,2p+1]
__device__ __align__(16) unsigned char g_Bfrag[2][16][8][2][32][16];

// SMEM: bias + A hi/lo fp16 tiles
static constexpr int OFF_BIAS = 0;                 // 512 floats
static constexpr int OFF_AH   = 4096;              // A hi tile 32KB
static constexpr int OFF_AL   = OFF_AH + 32768;    // A lo tile 32KB
static constexpr int SMEM_SIZE = OFF_AL + 32768;   // 69632 B -> 2 CTAs/SM

// ---------------------------------------------------------------------------
// helpers
// ---------------------------------------------------------------------------
__device__ __forceinline__ uint32_t smem_u32(const void* p) {
    uint32_t a;
    asm("{ .reg .u64 t; cvta.to.shared.u64 t, %1; cvt.u32.u64 %0, t; }"
        : "=r"(a) : "l"(p));
    return a;
}

// A tile: 128 rows x 256B, 16B chunks XOR-swizzled with (r&7)
__device__ __forceinline__ uint32_t tile_off(int r, int k0) {
    uint32_t ck = (uint32_t)(k0 >> 3) ^ (uint32_t)(r & 7);
    return (uint32_t)r * 256u + ck * 16u + (uint32_t)(k0 & 7) * 2u;
}

__device__ __forceinline__ float h_rt(float x) {
    return __half2float(__float2half_rn(x));
}

__device__ __forceinline__ uint32_t packh2(float a, float b) {
    __half2 t = __floats2half2_rn(a, b);
    return *reinterpret_cast<uint32_t*>(&t);
}

__device__ __forceinline__ void ldsm4(uint32_t* r, uint32_t addr) {
    asm volatile("ldmatrix.sync.aligned.m8n8.x4.shared.b16 {%0,%1,%2,%3}, [%4];"
                 : "=r"(r[0]), "=r"(r[1]), "=r"(r[2]), "=r"(r[3]) : "r"(addr));
}

__device__ __forceinline__ void mma16816(float* c, const uint32_t* a,
                                         uint32_t b0, uint32_t b1) {
    asm volatile(
        "mma.sync.aligned.m16n8k16.row.col.f32.f16.f16.f32 "
        "{%0,%1,%2,%3}, {%4,%5,%6,%7}, {%8,%9}, {%0,%1,%2,%3};"
        : "+f"(c[0]), "+f"(c[1]), "+f"(c[2]), "+f"(c[3])
        : "r"(a[0]), "r"(a[1]), "r"(a[2]), "r"(a[3]), "r"(b0), "r"(b1));
}

// ---------------------------------------------------------------------------
// Prep kernel: bake fp16(W) and fp16(W*W) into MMA-fragment order.
// m16n8k16 B frag: lane l holds b0 = B[k0..k0+1][n], b1 = B[k0+8..k0+9][n],
// n = l/4, k0 = (l%4)*2.
// ---------------------------------------------------------------------------
__global__ void prep_w_kernel(const float* __restrict__ W) {
    int id = blockIdx.x * blockDim.x + threadIdx.x;   // 0 .. 16383
    if (id >= 2 * 16 * 8 * 2 * 32) return;
    const int lane   = id & 31;
    const int p      = (id >> 5) & 1;
    const int ks     = (id >> 6) & 7;
    const int h      = (id >> 9) & 15;
    const int branch = id >> 13;                      // 0 = W, 1 = W*W

    uint32_t v[4];
    #pragma unroll
    for (int w = 0; w < 4; ++w) {
        int ni = 2 * p + (w >> 1);
        int n  = h * 32 + ni * 8 + (lane >> 2);
        int k  = ks * 16 + (w & 1) * 8 + (lane & 3) * 2;
        float w0 = W[n * XD + k];
        float w1 = W[n * XD + k + 1];
        if (branch) { w0 *= w0; w1 *= w1; }
        v[w] = packh2(w0, w1);
    }
    *(uint4*)&g_Bfrag[branch][h][ks][p][lane][0] =
        make_uint4(v[0], v[1], v[2], v[3]);
}

// ---------------------------------------------------------------------------
// Main kernel: CTA = 128 batch rows; warp = 64(M) x 32(N); 4 N-passes of 128
// ---------------------------------------------------------------------------
__global__ void __launch_bounds__(TPB, 2)
decoder_kernel(const float* __restrict__ mean, const float* __restrict__ logvar,
               const float* __restrict__ bias,
               float* __restrict__ out_mean, float* __restrict__ out_logv) {
    extern __shared__ __align__(16) char smem[];
    const uint32_t sb = smem_u32(smem);
    const int tid = threadIdx.x;
    const int t   = tid & 31;
    const int wid = tid >> 5;
    const int wm  = wid & 1;       // M group: rows wm*64 .. wm*64+63
    const int wn  = wid >> 1;      // N slice (32 cols) within 128-col pass
    const int row0 = blockIdx.x * MT;

    for (int i = tid; i < YD; i += TPB)
        ((float*)(smem + OFF_BIAS))[i] = bias[i];

    // A ldsm base offsets per mi-tile (16 rows each); per-ks advance via XOR
    uint32_t a_off[4];
    #pragma unroll
    for (int mi = 0; mi < 4; ++mi) {
        uint32_t row = (uint32_t)(wm * 64 + mi * 16 + (t & 15));
        a_off[mi] = row * 256u + (((uint32_t)(t >> 4) ^ (row & 7u)) << 4);
    }

    for (int branch = 0; branch < 2; ++branch) {
        if (branch) __syncthreads();   // A tiles about to be rewritten
        // ---- A conversion -> fp16 hi/lo swizzled tiles (A exact to 2^-23) ----
        const float* src = branch ? logvar : mean;
        for (int idx = tid; idx < MT * (XD / 2); idx += TPB) {
            int r  = idx >> 6;
            int k0 = (idx & 63) * 2;
            float2 v = *(const float2*)(src + (size_t)(row0 + r) * XD + k0);
            float v0 = v.x, v1 = v.y;
            if (branch) { v0 = __expf(v0); v1 = __expf(v1); }
            uint32_t sw = tile_off(r, k0);
            float h0 = h_rt(v0), h1 = h_rt(v1);
            *(uint32_t*)(smem + OFF_AH + sw) = packh2(h0, h1);
            *(uint32_t*)(smem + OFF_AL + sw) = packh2(v0 - h0, v1 - h1);
        }
        __syncthreads();

        for (int nc = 0; nc < 4; ++nc) {
            const int h = nc * 4 + wn;
            // uint4 element index: ((branch*16 + h)*8 + ks)*2*32 + p*32 + lane
            const uint4* bB = (const uint4*)g_Bfrag +
                (size_t)(branch * 16 + h) * (8 * 2 * 32) + t;

            float c[4][4][4] = {};

            // prefetch ks=0 B fragments (hi only; no lo needed)
            uint4 p0 = bB[0], p1 = bB[32];

            #pragma unroll
            for (int ks = 0; ks < 8; ++ks) {
                const uint32_t bh[8] = {p0.x, p0.y, p0.z, p0.w,
                                        p1.x, p1.y, p1.z, p1.w};
                if (ks < 7) {   // software pipeline next ks
                    p0 = bB[(ks + 1) * 64];
                    p1 = bB[(ks + 1) * 64 + 32];
                }
                const uint32_t kxor = ((uint32_t)(2 * ks) << 4);
                uint32_t ah[16], al[16];
                #pragma unroll
                for (int mi = 0; mi < 4; ++mi)
                    ldsm4(&ah[mi * 4], sb + OFF_AH + (a_off[mi] ^ kxor));
                #pragma unroll
                for (int mi = 0; mi < 4; ++mi)
                    ldsm4(&al[mi * 4], sb + OFF_AL + (a_off[mi] ^ kxor));

                // term-major: hh then lh; each accumulator hit every 16 MMAs
                #pragma unroll
                for (int mi = 0; mi < 4; ++mi)
                    #pragma unroll
                    for (int ni = 0; ni < 4; ++ni)
                        mma16816(c[mi][ni], &ah[mi * 4], bh[ni * 2], bh[ni * 2 + 1]);
                #pragma unroll
                for (int mi = 0; mi < 4; ++mi)
                    #pragma unroll
                    for (int ni = 0; ni < 4; ++ni)
                        mma16816(c[mi][ni], &al[mi * 4], bh[ni * 2], bh[ni * 2 + 1]);
            }

            // ---- epilogue (A tile untouched; no sync needed) ----
            const float* bs = (const float*)(smem + OFF_BIAS);
            #pragma unroll
            for (int mi = 0; mi < 4; ++mi) {
                const int r0 = row0 + wm * 64 + mi * 16 + (t >> 2);
                #pragma unroll
                for (int ni = 0; ni < 4; ++ni) {
                    const int col = nc * 128 + wn * 32 + ni * 8 + (t & 3) * 2;
                    float2 v0, v1;
                    v0.x = c[mi][ni][0]; v0.y = c[mi][ni][1];
                    v1.x = c[mi][ni][2]; v1.y = c[mi][ni][3];
                    if (branch == 0) {
                        float b0 = bs[col], b1 = bs[col + 1];
                        v0.x += b0; v0.y += b1;
                        v1.x += b0; v1.y += b1;
                        *(float2*)(out_mean + (size_t)r0 * YD + col)       = v0;
                        *(float2*)(out_mean + (size_t)(r0 + 8) * YD + col) = v1;
                    } else {
                        v0.x = __logf(v0.x); v0.y = __logf(v0.y);
                        v1.x = __logf(v1.x); v1.y = __logf(v1.y);
                        *(float2*)(out_logv + (size_t)r0 * YD + col)       = v0;
                        *(float2*)(out_logv + (size_t)(r0 + 8) * YD + col) = v1;
                    }
                }
            }
        }
    }
}

// ---------------------------------------------------------------------------
// Launch
// ---------------------------------------------------------------------------
extern "C" void kernel_launch(void* const* d_in, const int* in_sizes, int n_in,
                              void* d_out, int out_size) {
    const float* mean   = (const float*)d_in[0];
    const float* logvar = (const float*)d_in[1];
    const float* W      = (const float*)d_in[2];
    const float* bias   = (const float*)d_in[3];

    const int B = in_sizes[0] / XD;   // 131072
    float* out_mean = (float*)d_out;
    float* out_logv = out_mean + (size_t)B * YD;

    prep_w_kernel<<<64, TPB>>>(W);

    cudaFuncSetAttribute(decoder_kernel,
                         cudaFuncAttributeMaxDynamicSharedMemorySize, SMEM_SIZE);
    decoder_kernel<<<B / MT, TPB, SMEM_SIZE>>>(mean, logvar, bias,
                                               out_mean, out_logv);
}

// round 10
// speedup vs baseline: 1.7484x; 1.0009x over previous
#include <cuda_runtime.h>
#include <cuda_fp16.h>
#include <cstdint>
#include <cstddef>

// ============================================================================
// LinearDecoder: out_mean = mean @ W^T + b ; out_logv = log( exp(logvar) @ (W*W)^T )
// B=131072, X=128, Y=512.  Plain-sm_103 PTX (no tcgen05 in this harness).
// Round-7: fp16 2-term split (A = ah+al exact to 2^-23, B single fp16 ->
// error only from B rounding ~1.4e-4 norm-rel) + 2Mx4N warp tiling
// (B LDG redundancy 4x -> 2x). Cuts L1 bytes ~56% and MMAs 33% vs round-6.
// ============================================================================

static constexpr int XD  = 128;   // K
static constexpr int YD  = 512;   // N total
static constexpr int MT  = 128;   // M rows per CTA
static constexpr int TPB = 256;

// B fragments (fp16): [branch: W, W*W][h: 32-col slice 0..15][ks 0..7]
//                     [p 0..1][lane 0..31][16B = b0,b1 of tiles ni=2p,2p+1]
__device__ __align__(16) unsigned char g_Bfrag[2][16][8][2][32][16];

// SMEM: bias + A hi/lo fp16 tiles
static constexpr int OFF_BIAS = 0;                 // 512 floats
static constexpr int OFF_AH   = 4096;              // A hi tile 32KB
static constexpr int OFF_AL   = OFF_AH + 32768;    // A lo tile 32KB
static constexpr int SMEM_SIZE = OFF_AL + 32768;   // 69632 B -> 2 CTAs/SM

// ---------------------------------------------------------------------------
// helpers
// ---------------------------------------------------------------------------
__device__ __forceinline__ uint32_t smem_u32(const void* p) {
    uint32_t a;
    asm("{ .reg .u64 t; cvta.to.shared.u64 t, %1; cvt.u32.u64 %0, t; }"
        : "=r"(a) : "l"(p));
    return a;
}

// A tile: 128 rows x 256B, 16B chunks XOR-swizzled with (r&7)
__device__ __forceinline__ uint32_t tile_off(int r, int k0) {
    uint32_t ck = (uint32_t)(k0 >> 3) ^ (uint32_t)(r & 7);
    return (uint32_t)r * 256u + ck * 16u + (uint32_t)(k0 & 7) * 2u;
}

__device__ __forceinline__ float h_rt(float x) {
    return __half2float(__float2half_rn(x));
}

__device__ __forceinline__ uint32_t packh2(float a, float b) {
    __half2 t = __floats2half2_rn(a, b);
    return *reinterpret_cast<uint32_t*>(&t);
}

__device__ __forceinline__ void ldsm4(uint32_t* r, uint32_t addr) {
    asm volatile("ldmatrix.sync.aligned.m8n8.x4.shared.b16 {%0,%1,%2,%3}, [%4];"
                 : "=r"(r[0]), "=r"(r[1]), "=r"(r[2]), "=r"(r[3]) : "r"(addr));
}

__device__ __forceinline__ void mma16816(float* c, const uint32_t* a,
                                         uint32_t b0, uint32_t b1) {
    asm volatile(
        "mma.sync.aligned.m16n8k16.row.col.f32.f16.f16.f32 "
        "{%0,%1,%2,%3}, {%4,%5,%6,%7}, {%8,%9}, {%0,%1,%2,%3};"
        : "+f"(c[0]), "+f"(c[1]), "+f"(c[2]), "+f"(c[3])
        : "r"(a[0]), "r"(a[1]), "r"(a[2]), "r"(a[3]), "r"(b0), "r"(b1));
}

// ---------------------------------------------------------------------------
// Prep kernel: bake fp16(W) and fp16(W*W) into MMA-fragment order.
// m16n8k16 B frag: lane l holds b0 = B[k0..k0+1][n], b1 = B[k0+8..k0+9][n],
// n = l/4, k0 = (l%4)*2.
// ---------------------------------------------------------------------------
__global__ void prep_w_kernel(const float* __restrict__ W) {
    int id = blockIdx.x * blockDim.x + threadIdx.x;   // 0 .. 16383
    if (id >= 2 * 16 * 8 * 2 * 32) return;
    const int lane   = id & 31;
    const int p      = (id >> 5) & 1;
    const int ks     = (id >> 6) & 7;
    const int h      = (id >> 9) & 15;
    const int branch = id >> 13;                      // 0 = W, 1 = W*W

    uint32_t v[4];
    #pragma unroll
    for (int w = 0; w < 4; ++w) {
        int ni = 2 * p + (w >> 1);
        int n  = h * 32 + ni * 8 + (lane >> 2);
        int k  = ks * 16 + (w & 1) * 8 + (lane & 3) * 2;
        float w0 = W[n * XD + k];
        float w1 = W[n * XD + k + 1];
        if (branch) { w0 *= w0; w1 *= w1; }
        v[w] = packh2(w0, w1);
    }
    *(uint4*)&g_Bfrag[branch][h][ks][p][lane][0] =
        make_uint4(v[0], v[1], v[2], v[3]);
}

// ---------------------------------------------------------------------------
// Main kernel: CTA = 128 batch rows; warp = 64(M) x 32(N); 4 N-passes of 128
// ---------------------------------------------------------------------------
__global__ void __launch_bounds__(TPB, 2)
decoder_kernel(const float* __restrict__ mean, const float* __restrict__ logvar,
               const float* __restrict__ bias,
               float* __restrict__ out_mean, float* __restrict__ out_logv) {
    extern __shared__ __align__(16) char smem[];
    const uint32_t sb = smem_u32(smem);
    const int tid = threadIdx.x;
    const int t   = tid & 31;
    const int wid = tid >> 5;
    const int wm  = wid & 1;       // M group: rows wm*64 .. wm*64+63
    const int wn  = wid >> 1;      // N slice (32 cols) within 128-col pass
    const int row0 = blockIdx.x * MT;

    for (int i = tid; i < YD; i += TPB)
        ((float*)(smem + OFF_BIAS))[i] = bias[i];

    // A ldsm base offsets per mi-tile (16 rows each); per-ks advance via XOR
    uint32_t a_off[4];
    #pragma unroll
    for (int mi = 0; mi < 4; ++mi) {
        uint32_t row = (uint32_t)(wm * 64 + mi * 16 + (t & 15));
        a_off[mi] = row * 256u + (((uint32_t)(t >> 4) ^ (row & 7u)) << 4);
    }

    for (int branch = 0; branch < 2; ++branch) {
        if (branch) __syncthreads();   // A tiles about to be rewritten
        // ---- A conversion -> fp16 hi/lo swizzled tiles (A exact to 2^-23) ----
        const float* src = branch ? logvar : mean;
        for (int idx = tid; idx < MT * (XD / 2); idx += TPB) {
            int r  = idx >> 6;
            int k0 = (idx & 63) * 2;
            float2 v = *(const float2*)(src + (size_t)(row0 + r) * XD + k0);
            float v0 = v.x, v1 = v.y;
            if (branch) { v0 = __expf(v0); v1 = __expf(v1); }
            uint32_t sw = tile_off(r, k0);
            float h0 = h_rt(v0), h1 = h_rt(v1);
            *(uint32_t*)(smem + OFF_AH + sw) = packh2(h0, h1);
            *(uint32_t*)(smem + OFF_AL + sw) = packh2(v0 - h0, v1 - h1);
        }
        __syncthreads();

        for (int nc = 0; nc < 4; ++nc) {
            const int h = nc * 4 + wn;
            // uint4 element index: ((branch*16 + h)*8 + ks)*2*32 + p*32 + lane
            const uint4* bB = (const uint4*)g_Bfrag +
                (size_t)(branch * 16 + h) * (8 * 2 * 32) + t;

            float c[4][4][4] = {};

            // prefetch ks=0 B fragments (hi only; no lo needed)
            uint4 p0 = bB[0], p1 = bB[32];

            #pragma unroll
            for (int ks = 0; ks < 8; ++ks) {
                const uint32_t bh[8] = {p0.x, p0.y, p0.z, p0.w,
                                        p1.x, p1.y, p1.z, p1.w};
                if (ks < 7) {   // software pipeline next ks
                    p0 = bB[(ks + 1) * 64];
                    p1 = bB[(ks + 1) * 64 + 32];
                }
                const uint32_t kxor = ((uint32_t)(2 * ks) << 4);
                uint32_t ah[16], al[16];
                #pragma unroll
                for (int mi = 0; mi < 4; ++mi)
                    ldsm4(&ah[mi * 4], sb + OFF_AH + (a_off[mi] ^ kxor));
                #pragma unroll
                for (int mi = 0; mi < 4; ++mi)
                    ldsm4(&al[mi * 4], sb + OFF_AL + (a_off[mi] ^ kxor));

                // term-major: hh then lh; each accumulator hit every 16 MMAs
                #pragma unroll
                for (int mi = 0; mi < 4; ++mi)
                    #pragma unroll
                    for (int ni = 0; ni < 4; ++ni)
                        mma16816(c[mi][ni], &ah[mi * 4], bh[ni * 2], bh[ni * 2 + 1]);
                #pragma unroll
                for (int mi = 0; mi < 4; ++mi)
                    #pragma unroll
                    for (int ni = 0; ni < 4; ++ni)
                        mma16816(c[mi][ni], &al[mi * 4], bh[ni * 2], bh[ni * 2 + 1]);
            }

            // ---- epilogue (A tile untouched; no sync needed) ----
            const float* bs = (const float*)(smem + OFF_BIAS);
            #pragma unroll
            for (int mi = 0; mi < 4; ++mi) {
                const int r0 = row0 + wm * 64 + mi * 16 + (t >> 2);
                #pragma unroll
                for (int ni = 0; ni < 4; ++ni) {
                    const int col = nc * 128 + wn * 32 + ni * 8 + (t & 3) * 2;
                    float2 v0, v1;
                    v0.x = c[mi][ni][0]; v0.y = c[mi][ni][1];
                    v1.x = c[mi][ni][2]; v1.y = c[mi][ni][3];
                    if (branch == 0) {
                        float b0 = bs[col], b1 = bs[col + 1];
                        v0.x += b0; v0.y += b1;
                        v1.x += b0; v1.y += b1;
                        *(float2*)(out_mean + (size_t)r0 * YD + col)       = v0;
                        *(float2*)(out_mean + (size_t)(r0 + 8) * YD + col) = v1;
                    } else {
                        v0.x = __logf(v0.x); v0.y = __logf(v0.y);
                        v1.x = __logf(v1.x); v1.y = __logf(v1.y);
                        *(float2*)(out_logv + (size_t)r0 * YD + col)       = v0;
                        *(float2*)(out_logv + (size_t)(r0 + 8) * YD + col) = v1;
                    }
                }
            }
        }
    }
}

// ---------------------------------------------------------------------------
// Launch
// ---------------------------------------------------------------------------
extern "C" void kernel_launch(void* const* d_in, const int* in_sizes, int n_in,
                              void* d_out, int out_size) {
    const float* mean   = (const float*)d_in[0];
    const float* logvar = (const float*)d_in[1];
    const float* W      = (const float*)d_in[2];
    const float* bias   = (const float*)d_in[3];

    const int B = in_sizes[0] / XD;   // 131072
    float* out_mean = (float*)d_out;
    float* out_logv = out_mean + (size_t)B * YD;

    prep_w_kernel<<<64, TPB>>>(W);

    cudaFuncSetAttribute(decoder_kernel,
                         cudaFuncAttributeMaxDynamicSharedMemorySize, SMEM_SIZE);
    decoder_kernel<<<B / MT, TPB, SMEM_SIZE>>>(mean, logvar, bias,
                                               out_mean, out_logv);
}

// round 15
// speedup vs baseline: 1.7551x; 1.0038x over previous
#include <cuda_runtime.h>
#include <cuda_fp16.h>
#include <cstdint>
#include <cstddef>

// ============================================================================
// LinearDecoder: out_mean = mean @ W^T + b ; out_logv = log( exp(logvar) @ (W*W)^T )
// B=131072, X=128, Y=512.  Plain-sm_103 PTX (no tcgen05 in this harness).
// Round-7: fp16 2-term split (A = ah+al exact to 2^-23, B single fp16 ->
// error only from B rounding ~1.4e-4 norm-rel) + 2Mx4N warp tiling
// (B LDG redundancy 4x -> 2x). Cuts L1 bytes ~56% and MMAs 33% vs round-6.
// ============================================================================

static constexpr int XD  = 128;   // K
static constexpr int YD  = 512;   // N total
static constexpr int MT  = 128;   // M rows per CTA
static constexpr int TPB = 256;

// B fragments (fp16): [branch: W, W*W][h: 32-col slice 0..15][ks 0..7]
//                     [p 0..1][lane 0..31][16B = b0,b1 of tiles ni=2p,2p+1]
__device__ __align__(16) unsigned char g_Bfrag[2][16][8][2][32][16];

// SMEM: bias + A hi/lo fp16 tiles
static constexpr int OFF_BIAS = 0;                 // 512 floats
static constexpr int OFF_AH   = 4096;              // A hi tile 32KB
static constexpr int OFF_AL   = OFF_AH + 32768;    // A lo tile 32KB
static constexpr int SMEM_SIZE = OFF_AL + 32768;   // 69632 B -> 2 CTAs/SM

// ---------------------------------------------------------------------------
// helpers
// ---------------------------------------------------------------------------
__device__ __forceinline__ uint32_t smem_u32(const void* p) {
    uint32_t a;
    asm("{ .reg .u64 t; cvta.to.shared.u64 t, %1; cvt.u32.u64 %0, t; }"
        : "=r"(a) : "l"(p));
    return a;
}

// A tile: 128 rows x 256B, 16B chunks XOR-swizzled with (r&7)
__device__ __forceinline__ uint32_t tile_off(int r, int k0) {
    uint32_t ck = (uint32_t)(k0 >> 3) ^ (uint32_t)(r & 7);
    return (uint32_t)r * 256u + ck * 16u + (uint32_t)(k0 & 7) * 2u;
}

__device__ __forceinline__ float h_rt(float x) {
    return __half2float(__float2half_rn(x));
}

__device__ __forceinline__ uint32_t packh2(float a, float b) {
    __half2 t = __floats2half2_rn(a, b);
    return *reinterpret_cast<uint32_t*>(&t);
}

__device__ __forceinline__ void ldsm4(uint32_t* r, uint32_t addr) {
    asm volatile("ldmatrix.sync.aligned.m8n8.x4.shared.b16 {%0,%1,%2,%3}, [%4];"
                 : "=r"(r[0]), "=r"(r[1]), "=r"(r[2]), "=r"(r[3]) : "r"(addr));
}

__device__ __forceinline__ void mma16816(float* c, const uint32_t* a,
                                         uint32_t b0, uint32_t b1) {
    asm volatile(
        "mma.sync.aligned.m16n8k16.row.col.f32.f16.f16.f32 "
        "{%0,%1,%2,%3}, {%4,%5,%6,%7}, {%8,%9}, {%0,%1,%2,%3};"
        : "+f"(c[0]), "+f"(c[1]), "+f"(c[2]), "+f"(c[3])
        : "r"(a[0]), "r"(a[1]), "r"(a[2]), "r"(a[3]), "r"(b0), "r"(b1));
}

// ---------------------------------------------------------------------------
// Prep kernel: bake fp16(W) and fp16(W*W) into MMA-fragment order.
// m16n8k16 B frag: lane l holds b0 = B[k0..k0+1][n], b1 = B[k0+8..k0+9][n],
// n = l/4, k0 = (l%4)*2.
// ---------------------------------------------------------------------------
__global__ void prep_w_kernel(const float* __restrict__ W) {
    int id = blockIdx.x * blockDim.x + threadIdx.x;   // 0 .. 16383
    if (id >= 2 * 16 * 8 * 2 * 32) return;
    const int lane   = id & 31;
    const int p      = (id >> 5) & 1;
    const int ks     = (id >> 6) & 7;
    const int h      = (id >> 9) & 15;
    const int branch = id >> 13;                      // 0 = W, 1 = W*W

    uint32_t v[4];
    #pragma unroll
    for (int w = 0; w < 4; ++w) {
        int ni = 2 * p + (w >> 1);
        int n  = h * 32 + ni * 8 + (lane >> 2);
        int k  = ks * 16 + (w & 1) * 8 + (lane & 3) * 2;
        float w0 = W[n * XD + k];
        float w1 = W[n * XD + k + 1];
        if (branch) { w0 *= w0; w1 *= w1; }
        v[w] = packh2(w0, w1);
    }
    *(uint4*)&g_Bfrag[branch][h][ks][p][lane][0] =
        make_uint4(v[0], v[1], v[2], v[3]);
}

// ---------------------------------------------------------------------------
// Main kernel: CTA = 128 batch rows; warp = 64(M) x 32(N); 4 N-passes of 128
// ---------------------------------------------------------------------------
__global__ void __launch_bounds__(TPB, 2)
decoder_kernel(const float* __restrict__ mean, const float* __restrict__ logvar,
               const float* __restrict__ bias,
               float* __restrict__ out_mean, float* __restrict__ out_logv) {
    extern __shared__ __align__(16) char smem[];
    const uint32_t sb = smem_u32(smem);
    const int tid = threadIdx.x;
    const int t   = tid & 31;
    const int wid = tid >> 5;
    const int wm  = wid & 1;       // M group: rows wm*64 .. wm*64+63
    const int wn  = wid >> 1;      // N slice (32 cols) within 128-col pass
    const int row0 = blockIdx.x * MT;

    for (int i = tid; i < YD; i += TPB)
        ((float*)(smem + OFF_BIAS))[i] = bias[i];

    // A ldsm base offsets per mi-tile (16 rows each); per-ks advance via XOR
    uint32_t a_off[4];
    #pragma unroll
    for (int mi = 0; mi < 4; ++mi) {
        uint32_t row = (uint32_t)(wm * 64 + mi * 16 + (t & 15));
        a_off[mi] = row * 256u + (((uint32_t)(t >> 4) ^ (row & 7u)) << 4);
    }

    for (int branch = 0; branch < 2; ++branch) {
        if (branch) __syncthreads();   // A tiles about to be rewritten
        // ---- A conversion -> fp16 hi/lo swizzled tiles (A exact to 2^-23) ----
        const float* src = branch ? logvar : mean;
        for (int idx = tid; idx < MT * (XD / 2); idx += TPB) {
            int r  = idx >> 6;
            int k0 = (idx & 63) * 2;
            float2 v = *(const float2*)(src + (size_t)(row0 + r) * XD + k0);
            float v0 = v.x, v1 = v.y;
            if (branch) { v0 = __expf(v0); v1 = __expf(v1); }
            uint32_t sw = tile_off(r, k0);
            float h0 = h_rt(v0), h1 = h_rt(v1);
            *(uint32_t*)(smem + OFF_AH + sw) = packh2(h0, h1);
            *(uint32_t*)(smem + OFF_AL + sw) = packh2(v0 - h0, v1 - h1);
        }
        __syncthreads();

        for (int nc = 0; nc < 4; ++nc) {
            const int h = nc * 4 + wn;
            // uint4 element index: ((branch*16 + h)*8 + ks)*2*32 + p*32 + lane
            const uint4* bB = (const uint4*)g_Bfrag +
                (size_t)(branch * 16 + h) * (8 * 2 * 32) + t;

            float c[4][4][4] = {};

            // prefetch ks=0 B fragments (hi only; no lo needed)
            uint4 p0 = bB[0], p1 = bB[32];

            #pragma unroll
            for (int ks = 0; ks < 8; ++ks) {
                const uint32_t bh[8] = {p0.x, p0.y, p0.z, p0.w,
                                        p1.x, p1.y, p1.z, p1.w};
                if (ks < 7) {   // software pipeline next ks
                    p0 = bB[(ks + 1) * 64];
                    p1 = bB[(ks + 1) * 64 + 32];
                }
                const uint32_t kxor = ((uint32_t)(2 * ks) << 4);
                uint32_t ah[16], al[16];
                #pragma unroll
                for (int mi = 0; mi < 4; ++mi)
                    ldsm4(&ah[mi * 4], sb + OFF_AH + (a_off[mi] ^ kxor));
                #pragma unroll
                for (int mi = 0; mi < 4; ++mi)
                    ldsm4(&al[mi * 4], sb + OFF_AL + (a_off[mi] ^ kxor));

                // term-major: hh then lh; each accumulator hit every 16 MMAs
                #pragma unroll
                for (int mi = 0; mi < 4; ++mi)
                    #pragma unroll
                    for (int ni = 0; ni < 4; ++ni)
                        mma16816(c[mi][ni], &ah[mi * 4], bh[ni * 2], bh[ni * 2 + 1]);
                #pragma unroll
                for (int mi = 0; mi < 4; ++mi)
                    #pragma unroll
                    for (int ni = 0; ni < 4; ++ni)
                        mma16816(c[mi][ni], &al[mi * 4], bh[ni * 2], bh[ni * 2 + 1]);
            }

            // ---- epilogue (A tile untouched; no sync needed) ----
            const float* bs = (const float*)(smem + OFF_BIAS);
            #pragma unroll
            for (int mi = 0; mi < 4; ++mi) {
                const int r0 = row0 + wm * 64 + mi * 16 + (t >> 2);
                #pragma unroll
                for (int ni = 0; ni < 4; ++ni) {
                    const int col = nc * 128 + wn * 32 + ni * 8 + (t & 3) * 2;
                    float2 v0, v1;
                    v0.x = c[mi][ni][0]; v0.y = c[mi][ni][1];
                    v1.x = c[mi][ni][2]; v1.y = c[mi][ni][3];
                    if (branch == 0) {
                        float b0 = bs[col], b1 = bs[col + 1];
                        v0.x += b0; v0.y += b1;
                        v1.x += b0; v1.y += b1;
                        *(float2*)(out_mean + (size_t)r0 * YD + col)       = v0;
                        *(float2*)(out_mean + (size_t)(r0 + 8) * YD + col) = v1;
                    } else {
                        v0.x = __logf(v0.x); v0.y = __logf(v0.y);
                        v1.x = __logf(v1.x); v1.y = __logf(v1.y);
                        *(float2*)(out_logv + (size_t)r0 * YD + col)       = v0;
                        *(float2*)(out_logv + (size_t)(r0 + 8) * YD + col) = v1;
                    }
                }
            }
        }
    }
}

// ---------------------------------------------------------------------------
// Launch
// ---------------------------------------------------------------------------
extern "C" void kernel_launch(void* const* d_in, const int* in_sizes, int n_in,
                              void* d_out, int out_size) {
    const float* mean   = (const float*)d_in[0];
    const float* logvar = (const float*)d_in[1];
    const float* W      = (const float*)d_in[2];
    const float* bias   = (const float*)d_in[3];

    const int B = in_sizes[0] / XD;   // 131072
    float* out_mean = (float*)d_out;
    float* out_logv = out_mean + (size_t)B * YD;

    prep_w_kernel<<<64, TPB>>>(W);

    cudaFuncSetAttribute(decoder_kernel,
                         cudaFuncAttributeMaxDynamicSharedMemorySize, SMEM_SIZE);
    decoder_kernel<<<B / MT, TPB, SMEM_SIZE>>>(mean, logvar, bias,
                                               out_mean, out_logv);
}